// round 1
// baseline (speedup 1.0000x reference)
#include <cuda_runtime.h>

// ButterflyLinear: 12 butterfly stages on N=4096, TOKENS=8192.
// Key insight: stage 0 pairs (j, j^1); stages 1..11 all pair (j, j^2).
// => transform is block-diagonal in 4-element groups. Precompute the 4x4
// per-group matrix A_k once, then out = blockdiag(A) * x + bias.

#define TOKENS 8192
#define NCOLS  4096
#define DEPTH  12
#define GROUPS (NCOLS / 4)   // 1024
#define PAIRS  (NCOLS / 2)   // 2048 factor pairs per stage
#define T_PER  16            // tokens per thread in apply kernel

// Scratch: 1024 groups x 4 rows (each row = float4) = 64 KB
__device__ float4 g_A[GROUPS * 4];

// ---------------------------------------------------------------------------
// Kernel 1: fold the 12 stage matrices into one 4x4 per group.
// factors layout: F[stage][pair][c][d], flattened ((s*PAIRS + p)*2 + c)*2 + d
// Stage transform semantics: y[d] = sum_c pair_in[c] * f[c][d]
// ---------------------------------------------------------------------------
__global__ void butterfly_precompute(const float* __restrict__ F) {
    int g = blockIdx.x * blockDim.x + threadIdx.x;
    if (g >= GROUPS) return;

    float A[4][4];

    // Stage 0: mixes (0,1) with pair p=2g, and (2,3) with pair p=2g+1.
    {
        const float* f0 = F + (0 * PAIRS + 2 * g) * 4;
        const float* f1 = F + (0 * PAIRS + 2 * g + 1) * 4;
        // f[c][d]: f[0][0]=f[0], f[0][1]=f[1], f[1][0]=f[2], f[1][1]=f[3]
        A[0][0] = f0[0]; A[0][1] = f0[2]; A[0][2] = 0.f;   A[0][3] = 0.f;
        A[1][0] = f0[1]; A[1][1] = f0[3]; A[1][2] = 0.f;   A[1][3] = 0.f;
        A[2][0] = 0.f;   A[2][1] = 0.f;   A[2][2] = f1[0]; A[2][3] = f1[2];
        A[3][0] = 0.f;   A[3][1] = 0.f;   A[3][2] = f1[1]; A[3][3] = f1[3];
    }

    int j0 = 4 * g;
    #pragma unroll
    for (int s = 1; s < DEPTH; s++) {
        int block = 1 << (s + 1);
        // pair A: elements (0,2) of the group; pair B: elements (1,3)
        int pA = ((j0 >> (s + 1)) << s) | ((j0 & (block - 1)) >> 2);
        int pB = pA + (1 << (s - 1));
        const float* fA = F + (s * PAIRS + pA) * 4;
        const float* fB = F + (s * PAIRS + pB) * 4;
        float a00 = fA[0], a01 = fA[1], a10 = fA[2], a11 = fA[3];
        float b00 = fB[0], b01 = fB[1], b10 = fB[2], b11 = fB[3];
        #pragma unroll
        for (int e = 0; e < 4; e++) {
            float r0 = A[0][e], r1 = A[1][e], r2 = A[2][e], r3 = A[3][e];
            A[0][e] = a00 * r0 + a10 * r2;   // y0 = x0*f[0][0] + x2*f[1][0]
            A[2][e] = a01 * r0 + a11 * r2;   // y2 = x0*f[0][1] + x2*f[1][1]
            A[1][e] = b00 * r1 + b10 * r3;
            A[3][e] = b01 * r1 + b11 * r3;
        }
    }

    #pragma unroll
    for (int d = 0; d < 4; d++)
        g_A[g * 4 + d] = make_float4(A[d][0], A[d][1], A[d][2], A[d][3]);
}

// ---------------------------------------------------------------------------
// Kernel 2: out[t, 4g+d] = sum_e A_g[d][e] * x[t, 4g+e] + bias[4g+d]
// One thread per group, T_PER tokens each. float4 in/out, fully coalesced.
// ---------------------------------------------------------------------------
__global__ void __launch_bounds__(256)
butterfly_apply(const float4* __restrict__ x,
                const float4* __restrict__ bias4,
                float4* __restrict__ out) {
    int g  = blockIdx.x * blockDim.x + threadIdx.x;  // 0..GROUPS-1
    int t0 = blockIdx.y * T_PER;

    float4 a0 = g_A[g * 4 + 0];
    float4 a1 = g_A[g * 4 + 1];
    float4 a2 = g_A[g * 4 + 2];
    float4 a3 = g_A[g * 4 + 3];
    float4 b  = bias4[g];

    const float4* xp = x   + (size_t)t0 * GROUPS + g;
    float4*       op = out + (size_t)t0 * GROUPS + g;

    #pragma unroll 4
    for (int i = 0; i < T_PER; i++) {
        float4 v = xp[(size_t)i * GROUPS];
        float4 r;
        r.x = b.x + a0.x * v.x + a0.y * v.y + a0.z * v.z + a0.w * v.w;
        r.y = b.y + a1.x * v.x + a1.y * v.y + a1.z * v.z + a1.w * v.w;
        r.z = b.z + a2.x * v.x + a2.y * v.y + a2.z * v.z + a2.w * v.w;
        r.w = b.w + a3.x * v.x + a3.y * v.y + a3.z * v.z + a3.w * v.w;
        op[(size_t)i * GROUPS] = r;
    }
}

// ---------------------------------------------------------------------------
extern "C" void kernel_launch(void* const* d_in, const int* in_sizes, int n_in,
                              void* d_out, int out_size) {
    // Defensive input identification by element count.
    const float* x = nullptr;
    const float* factors = nullptr;
    const float* bias = nullptr;
    for (int i = 0; i < n_in; i++) {
        if (in_sizes[i] == TOKENS * NCOLS)            x = (const float*)d_in[i];
        else if (in_sizes[i] == DEPTH * PAIRS * 4)    factors = (const float*)d_in[i];
        else if (in_sizes[i] == NCOLS)                bias = (const float*)d_in[i];
    }

    butterfly_precompute<<<(GROUPS + 255) / 256, 256>>>(factors);

    dim3 grid(GROUPS / 256, TOKENS / T_PER);
    butterfly_apply<<<grid, 256>>>((const float4*)x,
                                   (const float4*)bias,
                                   (float4*)d_out);
}

// round 2
// speedup vs baseline: 1.1277x; 1.1277x over previous
#include <cuda_runtime.h>

// ButterflyLinear: 12 butterfly stages on N=4096, TOKENS=8192.
// Stage 0 pairs (j, j^1); stages 1..11 all pair (j, j^2) => transform is
// block-diagonal in 4-element groups. Precompute 4x4 per-group matrix A_g
// once per replay, then out = blockdiag(A) * x + bias (pure streaming).

#define TOKENS 8192
#define NCOLS  4096
#define DEPTH  12
#define GROUPS (NCOLS / 4)   // 1024
#define PAIRS  (NCOLS / 2)   // 2048 factor pairs per stage
#define T_PER  16            // tokens per thread in apply kernel

// Scratch: 1024 groups x 4 rows (each row = float4) = 64 KB
__device__ float4 g_A[GROUPS * 4];

// ---------------------------------------------------------------------------
// Kernel 1: fold 12 stage matrices into one 4x4 per group.
// All 24 factor loads are issued up-front (addresses depend only on g) so
// the single DRAM round-trip is overlapped across MLP=24, instead of 24
// serial misses on a 4-block grid.
// factors layout: F[stage][pair][c][d] — each pair's 2x2 is one float4:
//   f.x=f[0][0], f.y=f[0][1], f.z=f[1][0], f.w=f[1][1]
// Stage semantics: y[d] = sum_c pair_in[c] * f[c][d]
// ---------------------------------------------------------------------------
__global__ void butterfly_precompute(const float4* __restrict__ F4) {
    int g = blockIdx.x * blockDim.x + threadIdx.x;
    if (g >= GROUPS) return;

    int j0 = 4 * g;

    // ---- front-batched loads: 24 independent float4 LDGs ----
    float4 fa[DEPTH], fb[DEPTH];
    fa[0] = F4[2 * g];
    fb[0] = F4[2 * g + 1];
    #pragma unroll
    for (int s = 1; s < DEPTH; s++) {
        int block = 1 << (s + 1);
        int pA = ((j0 >> (s + 1)) << s) | ((j0 & (block - 1)) >> 2);
        int pB = pA + (1 << (s - 1));
        fa[s] = F4[s * PAIRS + pA];
        fb[s] = F4[s * PAIRS + pB];
    }

    // ---- fold ----
    float A[4][4];
    {
        float4 f0 = fa[0], f1 = fb[0];
        A[0][0] = f0.x; A[0][1] = f0.z; A[0][2] = 0.f;  A[0][3] = 0.f;
        A[1][0] = f0.y; A[1][1] = f0.w; A[1][2] = 0.f;  A[1][3] = 0.f;
        A[2][0] = 0.f;  A[2][1] = 0.f;  A[2][2] = f1.x; A[2][3] = f1.z;
        A[3][0] = 0.f;  A[3][1] = 0.f;  A[3][2] = f1.y; A[3][3] = f1.w;
    }

    #pragma unroll
    for (int s = 1; s < DEPTH; s++) {
        float a00 = fa[s].x, a01 = fa[s].y, a10 = fa[s].z, a11 = fa[s].w;
        float b00 = fb[s].x, b01 = fb[s].y, b10 = fb[s].z, b11 = fb[s].w;
        #pragma unroll
        for (int e = 0; e < 4; e++) {
            float r0 = A[0][e], r1 = A[1][e], r2 = A[2][e], r3 = A[3][e];
            A[0][e] = a00 * r0 + a10 * r2;   // y0 = x0*f[0][0] + x2*f[1][0]
            A[2][e] = a01 * r0 + a11 * r2;   // y2 = x0*f[0][1] + x2*f[1][1]
            A[1][e] = b00 * r1 + b10 * r3;
            A[3][e] = b01 * r1 + b11 * r3;
        }
    }

    #pragma unroll
    for (int d = 0; d < 4; d++)
        g_A[g * 4 + d] = make_float4(A[d][0], A[d][1], A[d][2], A[d][3]);
}

// ---------------------------------------------------------------------------
// Kernel 2: out[t, 4g+d] = sum_e A_g[d][e] * x[t, 4g+e] + bias[4g+d]
// Batch-of-4 load/compute/store with streaming cache hints: x/out are
// 128 MiB each with zero reuse — .cs keeps them from thrashing L2.
// ---------------------------------------------------------------------------
__global__ void __launch_bounds__(256)
butterfly_apply(const float4* __restrict__ x,
                const float4* __restrict__ bias4,
                float4* __restrict__ out) {
    int g  = blockIdx.x * blockDim.x + threadIdx.x;  // 0..GROUPS-1
    int t0 = blockIdx.y * T_PER;

    float4 a0 = g_A[g * 4 + 0];
    float4 a1 = g_A[g * 4 + 1];
    float4 a2 = g_A[g * 4 + 2];
    float4 a3 = g_A[g * 4 + 3];
    float4 b  = bias4[g];

    const float4* xp = x   + (size_t)t0 * GROUPS + g;
    float4*       op = out + (size_t)t0 * GROUPS + g;

    #pragma unroll
    for (int ii = 0; ii < T_PER; ii += 4) {
        // front-batched loads (MLP=4 per chunk, chunks overlap across SB slots)
        float4 v0 = __ldcs(xp + (size_t)(ii + 0) * GROUPS);
        float4 v1 = __ldcs(xp + (size_t)(ii + 1) * GROUPS);
        float4 v2 = __ldcs(xp + (size_t)(ii + 2) * GROUPS);
        float4 v3 = __ldcs(xp + (size_t)(ii + 3) * GROUPS);

        float4 r0, r1, r2, r3;
        r0.x = b.x + a0.x * v0.x + a0.y * v0.y + a0.z * v0.z + a0.w * v0.w;
        r0.y = b.y + a1.x * v0.x + a1.y * v0.y + a1.z * v0.z + a1.w * v0.w;
        r0.z = b.z + a2.x * v0.x + a2.y * v0.y + a2.z * v0.z + a2.w * v0.w;
        r0.w = b.w + a3.x * v0.x + a3.y * v0.y + a3.z * v0.z + a3.w * v0.w;

        r1.x = b.x + a0.x * v1.x + a0.y * v1.y + a0.z * v1.z + a0.w * v1.w;
        r1.y = b.y + a1.x * v1.x + a1.y * v1.y + a1.z * v1.z + a1.w * v1.w;
        r1.z = b.z + a2.x * v1.x + a2.y * v1.y + a2.z * v1.z + a2.w * v1.w;
        r1.w = b.w + a3.x * v1.x + a3.y * v1.y + a3.z * v1.z + a3.w * v1.w;

        r2.x = b.x + a0.x * v2.x + a0.y * v2.y + a0.z * v2.z + a0.w * v2.w;
        r2.y = b.y + a1.x * v2.x + a1.y * v2.y + a1.z * v2.z + a1.w * v2.w;
        r2.z = b.z + a2.x * v2.x + a2.y * v2.y + a2.z * v2.z + a2.w * v2.w;
        r2.w = b.w + a3.x * v2.x + a3.y * v2.y + a3.z * v2.z + a3.w * v2.w;

        r3.x = b.x + a0.x * v3.x + a0.y * v3.y + a0.z * v3.z + a0.w * v3.w;
        r3.y = b.y + a1.x * v3.x + a1.y * v3.y + a1.z * v3.z + a1.w * v3.w;
        r3.z = b.z + a2.x * v3.x + a2.y * v3.y + a2.z * v3.z + a2.w * v3.w;
        r3.w = b.w + a3.x * v3.x + a3.y * v3.y + a3.z * v3.z + a3.w * v3.w;

        __stcs(op + (size_t)(ii + 0) * GROUPS, r0);
        __stcs(op + (size_t)(ii + 1) * GROUPS, r1);
        __stcs(op + (size_t)(ii + 2) * GROUPS, r2);
        __stcs(op + (size_t)(ii + 3) * GROUPS, r3);
    }
}

// ---------------------------------------------------------------------------
extern "C" void kernel_launch(void* const* d_in, const int* in_sizes, int n_in,
                              void* d_out, int out_size) {
    const float* x = nullptr;
    const float* factors = nullptr;
    const float* bias = nullptr;
    for (int i = 0; i < n_in; i++) {
        if (in_sizes[i] == TOKENS * NCOLS)            x = (const float*)d_in[i];
        else if (in_sizes[i] == DEPTH * PAIRS * 4)    factors = (const float*)d_in[i];
        else if (in_sizes[i] == NCOLS)                bias = (const float*)d_in[i];
    }

    butterfly_precompute<<<(GROUPS + 255) / 256, 256>>>((const float4*)factors);

    dim3 grid(GROUPS / 256, TOKENS / T_PER);
    butterfly_apply<<<grid, 256>>>((const float4*)x,
                                   (const float4*)bias,
                                   (float4*)d_out);
}